// round 15
// baseline (speedup 1.0000x reference)
#include <cuda_runtime.h>
#include <cuda_fp16.h>
#include <stdint.h>

#define EMBED 1024
#define BATCH 4
#define SEQ   2048
#define MTOT  (BATCH * SEQ)   // 8192

#define BM 128
#define BN 128
#define BKH 32                 // fp16 k elements per stage
#define NTHREADS 256

#define ROWB   64              // bytes per SMEM row (XOR swizzle, no pad)
#define TILEB  (128 * ROWB)    // 8192 B per fp16 tile
#define STAGEB (2 * TILEB)     // 16384 B (A, B)
#define NSTAGE 4
#define SMEM_DYN (NSTAGE * STAGEB)  // 65536 B

#define SWZB(row, c) ((c) ^ ((((row) >> 1) & 3) << 4))

// ---------------- scratch (device globals; fp16 operands) ------------------
__device__ __align__(128) __half g_x [(size_t)MTOT * EMBED];
__device__ __align__(128) __half g_W [(size_t)3 * EMBED * EMBED];
__device__ __align__(128) __half g_Q [(size_t)MTOT * EMBED];
__device__ __align__(128) __half g_K [(size_t)MTOT * EMBED];
__device__ __align__(128) __half g_Vt[(size_t)BATCH * EMBED * SEQ];  // [b][e][s]
__device__ __align__(128) __half g_w [(size_t)BATCH * SEQ * SEQ];    // [b][q][k]

// per-(batch,row-block) completed scores tiles; zeroed in conv_k
__device__ int g_rowCnt[64];

// ---------------------------------------------------------------------------
__device__ __forceinline__ uint32_t smem_u32(const void* p) {
    uint32_t a;
    asm("{ .reg .u64 t; cvta.to.shared.u64 t, %1; cvt.u32.u64 %0, t; }"
        : "=r"(a) : "l"(p));
    return a;
}

__device__ __forceinline__ void cp16(uint32_t saddr, const void* g) {
    asm volatile("cp.async.cg.shared.global [%0], [%1], 16;"
                 :: "r"(saddr), "l"(g));
}

#define LDSM4(r0, r1, r2, r3, addr)                                          \
    asm volatile("ldmatrix.sync.aligned.m8n8.x4.shared.b16 {%0,%1,%2,%3}, [%4];" \
                 : "=r"(r0), "=r"(r1), "=r"(r2), "=r"(r3) : "r"(addr))

#define MMA16816(d, a0, a1, a2, a3, b0, b1)                                  \
    asm volatile("mma.sync.aligned.m16n8k16.row.col.f32.f16.f16.f32 "        \
                 "{%0,%1,%2,%3}, {%4,%5,%6,%7}, {%8,%9}, {%0,%1,%2,%3};"     \
                 : "+f"(d[0]), "+f"(d[1]), "+f"(d[2]), "+f"(d[3])            \
                 : "r"(a0), "r"(a1), "r"(a2), "r"(a3), "r"(b0), "r"(b1))

__device__ __forceinline__ uint32_t packh(__half a, __half b) {
    return (uint32_t)__half_as_ushort(a) | ((uint32_t)__half_as_ushort(b) << 16);
}

__device__ __forceinline__ int ld_acq(const int* p) {
    int v;
    asm volatile("ld.acquire.gpu.s32 %0, [%1];" : "=r"(v) : "l"(p) : "memory");
    return v;
}

// ---------------------------------------------------------------------------
// cp.async one K-chunk (32 fp16) of A and B tiles into a stage (1024 x 16B)
// ---------------------------------------------------------------------------
__device__ __forceinline__ void issue_chunk(
    uint32_t smStage,
    const __half* __restrict__ A, int lda, int rowBase,
    const __half* __restrict__ B, int ldb, int colBase, int k0)
{
    const int tid = threadIdx.x;
#pragma unroll
    for (int i = 0; i < 4; i++) {
        const int id   = tid + 256 * i;    // 0..1023
        const int tile = id >> 9;          // 0: A, 1: B
        const int row  = (id >> 2) & 127;
        const int cc   = id & 3;
        const __half* g = (tile ? B + (size_t)(colBase + row) * ldb
                                : A + (size_t)(rowBase + row) * lda) + k0 + cc * 8;
        cp16(smStage + tile * TILEB + row * ROWB + SWZB(row, cc * 16), g);
    }
    asm volatile("cp.async.commit_group;" ::: "memory");
}

// ---------------------------------------------------------------------------
// compute one stage: 2 k16-steps, warp tile 64x32 (8 warps, 2x4)
// ---------------------------------------------------------------------------
__device__ __forceinline__ void compute_stage(uint32_t sst, int mW, int nW,
                                              int rIn, int cInB,
                                              float acc[4][4][4])
{
#pragma unroll
    for (int ks = 0; ks < 2; ks++) {
        const int cIn = cInB + ks * 32;
        uint32_t bh[2][4];
#pragma unroll
        for (int p = 0; p < 2; p++) {
            const int row = nW + p * 16 + rIn;
            const uint32_t off = (uint32_t)(row * ROWB + SWZB(row, cIn));
            LDSM4(bh[p][0], bh[p][1], bh[p][2], bh[p][3], sst + TILEB + off);
        }
#pragma unroll
        for (int mt = 0; mt < 4; mt++) {
            const int row = mW + mt * 16 + rIn;
            const uint32_t off = (uint32_t)(row * ROWB + SWZB(row, cIn));
            uint32_t ah[4];
            LDSM4(ah[0], ah[1], ah[2], ah[3], sst + off);
#pragma unroll
            for (int nt = 0; nt < 4; nt++) {
                const int p = nt >> 1, s = nt & 1;
                MMA16816(acc[mt][nt], ah[0], ah[1], ah[2], ah[3],
                         bh[p][s], bh[p][s + 2]);
            }
        }
    }
}

// ---------------------------------------------------------------------------
// NT GEMM core: 128x128 tile, 4-stage cp.async ring, one barrier per stage
// ---------------------------------------------------------------------------
__device__ __forceinline__ void gemm_core(
    const __half* __restrict__ A, int lda, int rowBase,
    const __half* __restrict__ B, int ldb, int colBase,
    int Kdim, char* sm, float acc[4][4][4])
{
    const uint32_t smBase = smem_u32(sm);
    const int lane = threadIdx.x & 31;
    const int warp = threadIdx.x >> 5;
    const int mW = (warp >> 2) * 64, nW = (warp & 3) * 32;
    const int grp = lane >> 3;
    const int rIn = (grp & 1) * 8 + (lane & 7);
    const int cInB = (grp >> 1) * 16;

    const int NC = Kdim / BKH;
    issue_chunk(smBase,          A, lda, rowBase, B, ldb, colBase, 0);
    issue_chunk(smBase + STAGEB, A, lda, rowBase, B, ldb, colBase, BKH);

    int stage = 0;
    for (int c = 0; c < NC; c++) {
        if (c + 2 < NC) {
            const int s2 = (stage + 2) & 3;
            issue_chunk(smBase + s2 * STAGEB, A, lda, rowBase,
                        B, ldb, colBase, (c + 2) * BKH);
        } else {
            asm volatile("cp.async.commit_group;" ::: "memory");
        }
        asm volatile("cp.async.wait_group 2;" ::: "memory");
        __syncthreads();
        compute_stage(smBase + stage * STAGEB, mW, nW, rIn, cInB, acc);
        stage = (stage + 1) & 3;
    }
}

// ---------------------------------------------------------------------------
// Kernel 0: fp32 -> fp16 convert for x, Wq, Wk, Wv in ONE launch + zero flags
// ---------------------------------------------------------------------------
#define NX4 (MTOT * EMBED / 4)        // 2M
#define NW4 (EMBED * EMBED / 4)       // 256K
__global__ __launch_bounds__(256)
void conv_k(const float* __restrict__ x,  const float* __restrict__ Wq,
            const float* __restrict__ Wk, const float* __restrict__ Wv)
{
    if (blockIdx.x == 0 && threadIdx.x < 64) g_rowCnt[threadIdx.x] = 0;
    const int i = blockIdx.x * 256 + threadIdx.x;
    const float* in; __half* o; int idx;
    if (i < NX4)                { in = x;  o = g_x;           idx = i; }
    else if (i < NX4 + NW4)     { in = Wq; o = g_W;           idx = i - NX4; }
    else if (i < NX4 + 2 * NW4) { in = Wk; o = g_W + 4 * NW4; idx = i - NX4 - NW4; }
    else if (i < NX4 + 3 * NW4) { in = Wv; o = g_W + 8 * NW4; idx = i - NX4 - 2 * NW4; }
    else return;
    float4 v = reinterpret_cast<const float4*>(in)[idx];
    reinterpret_cast<uint2*>(o)[idx] =
        make_uint2(packh(__float2half(v.x), __float2half(v.y)),
                   packh(__float2half(v.z), __float2half(v.w)));
}

// ---------------------------------------------------------------------------
// Kernel 1: QKV projection (x @ W^T + b). z selects Q/K/V.
// V goes TRANSPOSED into g_Vt via SMEM staging.
// ---------------------------------------------------------------------------
__global__ __launch_bounds__(NTHREADS, 2)
void qkv_k(const float* __restrict__ bq, const float* __restrict__ bk,
           const float* __restrict__ bv)
{
    extern __shared__ char sm[];
    const int which = blockIdx.z;
    const float* bias = (which == 0) ? bq : (which == 1) ? bk : bv;
    const __half* W = g_W + (size_t)which * EMBED * EMBED;

    const int rowBase = blockIdx.y * BM;
    const int colBase = blockIdx.x * BN;

    float acc[4][4][4] = {};
    gemm_core(g_x, EMBED, rowBase, W, EMBED, colBase, EMBED, sm, acc);

    const int warp = threadIdx.x >> 5, lane = threadIdx.x & 31;
    const int mW = (warp >> 2) * 64, nW = (warp & 3) * 32;

    if (which < 2) {
        __half* o = (which == 0) ? g_Q : g_K;
#pragma unroll
        for (int mt = 0; mt < 4; mt++) {
#pragma unroll
            for (int nt = 0; nt < 4; nt++) {
                const int r0 = rowBase + mW + mt * 16 + (lane >> 2);
                const int c0 = colBase + nW + nt * 8 + 2 * (lane & 3);
                const float b0 = bias[c0], b1 = bias[c0 + 1];
                *reinterpret_cast<uint32_t*>(o + (size_t)r0 * EMBED + c0) =
                    packh(__float2half(acc[mt][nt][0] + b0),
                          __float2half(acc[mt][nt][1] + b1));
                *reinterpret_cast<uint32_t*>(o + (size_t)(r0 + 8) * EMBED + c0) =
                    packh(__float2half(acc[mt][nt][2] + b0),
                          __float2half(acc[mt][nt][3] + b1));
            }
        }
    } else {
        // V: transpose-stage in SMEM [e 128][s pitch 136], then coalesced out
        __syncthreads();
        __half* sh = reinterpret_cast<__half*>(sm);
#pragma unroll
        for (int mt = 0; mt < 4; mt++) {
#pragma unroll
            for (int nt = 0; nt < 4; nt++) {
                const int rr = mW + mt * 16 + (lane >> 2);   // s_rel
                const int cc = nW + nt * 8 + 2 * (lane & 3); // e_rel
                const float b0 = bias[colBase + cc], b1 = bias[colBase + cc + 1];
                sh[cc * 136 + rr]           = __float2half(acc[mt][nt][0] + b0);
                sh[(cc + 1) * 136 + rr]     = __float2half(acc[mt][nt][1] + b1);
                sh[cc * 136 + rr + 8]       = __float2half(acc[mt][nt][2] + b0);
                sh[(cc + 1) * 136 + rr + 8] = __float2half(acc[mt][nt][3] + b1);
            }
        }
        __syncthreads();
        const int b = rowBase >> 11;
        const int sBase = rowBase & (SEQ - 1);
        const int erow = threadIdx.x >> 1, half = threadIdx.x & 1;
        const uint32_t* src = reinterpret_cast<const uint32_t*>(sh + erow * 136 + half * 64);
        const size_t dstE = ((size_t)(b * EMBED + colBase + erow) * SEQ + sBase + half * 64) >> 1;
        uint32_t* d = reinterpret_cast<uint32_t*>(g_Vt) + dstE;
#pragma unroll
        for (int i = 0; i < 32; i++) d[i] = src[i];
    }
}

// ---------------------------------------------------------------------------
// softmax for one row (256 threads), prefix length L (multiple of 128)
// ---------------------------------------------------------------------------
__device__ __forceinline__ void softmax_row(float* __restrict__ p,
                                            __half* __restrict__ wh,
                                            int L, float* red)
{
    const int t = threadIdx.x;
    float mx = -1e30f;
    for (int k = t; k < L; k += 256) mx = fmaxf(mx, p[k]);
#pragma unroll
    for (int o = 16; o > 0; o >>= 1) mx = fmaxf(mx, __shfl_xor_sync(0xffffffffu, mx, o));
    if ((t & 31) == 0) red[t >> 5] = mx;
    __syncthreads();
    float mxall = red[0];
#pragma unroll
    for (int i = 1; i < 8; i++) mxall = fmaxf(mxall, red[i]);
    __syncthreads();

    float v[8];
    float s = 0.0f;
    {
        int i = 0;
        for (int k = t; k < L; k += 256, i++) { v[i] = __expf(p[k] - mxall); s += v[i]; }
    }
#pragma unroll
    for (int o = 16; o > 0; o >>= 1) s += __shfl_xor_sync(0xffffffffu, s, o);
    if ((t & 31) == 0) red[t >> 5] = s;
    __syncthreads();
    float total = 0.0f;
#pragma unroll
    for (int i = 0; i < 8; i++) total += red[i];
    const float inv = 1.0f / total;

    {
        int i = 0;
        for (int k = t; k < L; k += 256, i++) {
            const float w = v[i] * inv;
            p[k] = w;
            wh[k] = __float2half(w);
        }
    }
    for (int k = L + t; k < SEQ; k += 256) p[k] = 0.0f;  // fp32 wts tail zeros
    __syncthreads();
}

// ---------------------------------------------------------------------------
// Kernel 2: scores (lower-triangle tiles) + FUSED per-row-block softmax.
// After writing its tile, each CTA signals rowCnt[b,y]; once the row block
// is complete its CTAs (x=0..y) run 16-row softmax subgroups (g%(y+1)==x).
// ---------------------------------------------------------------------------
__global__ __launch_bounds__(NTHREADS, 2)
void scores_k(float* __restrict__ wts)
{
    const int x = blockIdx.x, y = blockIdx.y;
    if (x > y) return;                       // fully masked tile
    extern __shared__ char sm[];
    __shared__ float red[8];
    const int b = blockIdx.z;
    const __half* Q = g_Q + (size_t)b * SEQ * EMBED;
    const __half* K = g_K + (size_t)b * SEQ * EMBED;
    float* S = wts + (size_t)b * SEQ * SEQ;

    const int rowBase = y * BM;
    const int colBase = x * BN;

    float acc[4][4][4] = {};
    gemm_core(Q, EMBED, rowBase, K, EMBED, colBase, EMBED, sm, acc);

    const int warp = threadIdx.x >> 5, lane = threadIdx.x & 31;
    const int mW = (warp >> 2) * 64, nW = (warp & 3) * 32;
    const float scale = 0.03125f;

#pragma unroll
    for (int mt = 0; mt < 4; mt++) {
#pragma unroll
        for (int nt = 0; nt < 4; nt++) {
            const int q0 = rowBase + mW + mt * 16 + (lane >> 2);
            const int c0 = colBase + nW + nt * 8 + 2 * (lane & 3);
            float2 v0, v1;
            v0.x = acc[mt][nt][0] * scale + ((c0 + 0) > q0 ? -999.0f : 0.0f);
            v0.y = acc[mt][nt][1] * scale + ((c0 + 1) > q0 ? -999.0f : 0.0f);
            v1.x = acc[mt][nt][2] * scale + ((c0 + 0) > (q0 + 8) ? -999.0f : 0.0f);
            v1.y = acc[mt][nt][3] * scale + ((c0 + 1) > (q0 + 8) ? -999.0f : 0.0f);
            *(float2*)&S[(size_t)q0 * SEQ + c0]       = v0;
            *(float2*)&S[(size_t)(q0 + 8) * SEQ + c0] = v1;
        }
    }

    // signal tile done (release)
    __syncthreads();
    int* cnt = &g_rowCnt[b * 16 + y];
    if (threadIdx.x == 0) { __threadfence(); atomicAdd(cnt, 1); }

    // wait for whole row block (acquire), then fused softmax
    if (threadIdx.x == 0) {
        while (ld_acq(cnt) < y + 1) __nanosleep(64);
    }
    __syncthreads();

    const int L = (y + 1) * 128;
    for (int g = x; g < 8; g += y + 1) {
        const int row0 = b * SEQ + y * 128 + g * 16;
        for (int rr = 0; rr < 16; rr++) {
            const int row = row0 + rr;
            softmax_row(wts + (size_t)row * SEQ,
                        g_w + (size_t)row * SEQ, L, red);
        }
    }
}

// ---------------------------------------------------------------------------
// Kernel 4: out = w @ V via NT GEMM against Vt; K truncated causally.
// blockIdx.y REVERSED so longest-K CTAs launch first (tail balance).
// ---------------------------------------------------------------------------
__global__ __launch_bounds__(NTHREADS, 2)
void av_k(float* __restrict__ out)
{
    extern __shared__ char sm[];
    const int b = blockIdx.z;
    const __half* A  = g_w  + (size_t)b * SEQ * SEQ;
    const __half* Bv = g_Vt + (size_t)b * EMBED * SEQ;
    float* C = out + (size_t)b * SEQ * EMBED;

    const int by = (SEQ / BM - 1) - blockIdx.y;   // longest K first
    const int rowBase = by * BM;
    const int colBase = blockIdx.x * BN;
    const int Keff = rowBase + BM;                // causal truncation

    float acc[4][4][4] = {};
    gemm_core(A, SEQ, rowBase, Bv, SEQ, colBase, Keff, sm, acc);

    const int warp = threadIdx.x >> 5, lane = threadIdx.x & 31;
    const int mW = (warp >> 2) * 64, nW = (warp & 3) * 32;

#pragma unroll
    for (int mt = 0; mt < 4; mt++) {
#pragma unroll
        for (int nt = 0; nt < 4; nt++) {
            const int r0 = rowBase + mW + mt * 16 + (lane >> 2);
            const int c0 = colBase + nW + nt * 8 + 2 * (lane & 3);
            *(float2*)&C[(size_t)r0 * EMBED + c0] =
                make_float2(acc[mt][nt][0], acc[mt][nt][1]);
            *(float2*)&C[(size_t)(r0 + 8) * EMBED + c0] =
                make_float2(acc[mt][nt][2], acc[mt][nt][3]);
        }
    }
}

// ---------------------------------------------------------------------------
extern "C" void kernel_launch(void* const* d_in, const int* in_sizes, int n_in,
                              void* d_out, int out_size)
{
    const float* x  = (const float*)d_in[0];
    const float* Wq = (const float*)d_in[1];
    const float* bq = (const float*)d_in[2];
    const float* Wk = (const float*)d_in[3];
    const float* bk = (const float*)d_in[4];
    const float* Wv = (const float*)d_in[5];
    const float* bv = (const float*)d_in[6];

    float* out = (float*)d_out;
    float* wts = out + (size_t)MTOT * EMBED;

    cudaFuncSetAttribute(qkv_k,    cudaFuncAttributeMaxDynamicSharedMemorySize, SMEM_DYN);
    cudaFuncSetAttribute(scores_k, cudaFuncAttributeMaxDynamicSharedMemorySize, SMEM_DYN);
    cudaFuncSetAttribute(av_k,     cudaFuncAttributeMaxDynamicSharedMemorySize, SMEM_DYN);

    const int ntot = NX4 + 3 * NW4;
    conv_k<<<(ntot + 255) / 256, 256>>>(x, Wq, Wk, Wv);

    qkv_k<<<dim3(EMBED / BN, MTOT / BM, 3), NTHREADS, SMEM_DYN>>>(bq, bk, bv);
    scores_k<<<dim3(SEQ / BN, SEQ / BM, BATCH), NTHREADS, SMEM_DYN>>>(wts);
    av_k<<<dim3(EMBED / BN, SEQ / BM, BATCH), NTHREADS, SMEM_DYN>>>(out);
}

// round 16
// speedup vs baseline: 1.3432x; 1.3432x over previous
#include <cuda_runtime.h>
#include <cuda_fp16.h>
#include <stdint.h>

#define EMBED 1024
#define BATCH 4
#define SEQ   2048
#define MTOT  (BATCH * SEQ)   // 8192

#define BM 128
#define BN 128
#define BKH 32                 // fp16 k elements per stage
#define NTHREADS 256

#define ROWB   64              // bytes per SMEM row (XOR swizzle, no pad)
#define TILEB  (128 * ROWB)    // 8192 B per fp16 tile
#define STAGEB (2 * TILEB)     // 16384 B (A, B)
#define NSTAGE 4
#define SMEM_DYN (NSTAGE * STAGEB)  // 65536 B

#define SWZB(row, c) ((c) ^ ((((row) >> 1) & 3) << 4))

// ---------------- scratch (device globals; fp16 operands) ------------------
__device__ __align__(128) __half g_x [(size_t)MTOT * EMBED];
__device__ __align__(128) __half g_W [(size_t)3 * EMBED * EMBED];
__device__ __align__(128) __half g_Q [(size_t)MTOT * EMBED];
__device__ __align__(128) __half g_K [(size_t)MTOT * EMBED];
__device__ __align__(128) __half g_Vt[(size_t)BATCH * EMBED * SEQ];  // [b][e][s]
__device__ __align__(128) __half g_w [(size_t)BATCH * SEQ * SEQ];    // [b][q][k]

// ---------------------------------------------------------------------------
__device__ __forceinline__ uint32_t smem_u32(const void* p) {
    uint32_t a;
    asm("{ .reg .u64 t; cvta.to.shared.u64 t, %1; cvt.u32.u64 %0, t; }"
        : "=r"(a) : "l"(p));
    return a;
}

__device__ __forceinline__ void cp16(uint32_t saddr, const void* g) {
    asm volatile("cp.async.cg.shared.global [%0], [%1], 16;"
                 :: "r"(saddr), "l"(g));
}

#define LDSM4(r0, r1, r2, r3, addr)                                          \
    asm volatile("ldmatrix.sync.aligned.m8n8.x4.shared.b16 {%0,%1,%2,%3}, [%4];" \
                 : "=r"(r0), "=r"(r1), "=r"(r2), "=r"(r3) : "r"(addr))

#define MMA16816(d, a0, a1, a2, a3, b0, b1)                                  \
    asm volatile("mma.sync.aligned.m16n8k16.row.col.f32.f16.f16.f32 "        \
                 "{%0,%1,%2,%3}, {%4,%5,%6,%7}, {%8,%9}, {%0,%1,%2,%3};"     \
                 : "+f"(d[0]), "+f"(d[1]), "+f"(d[2]), "+f"(d[3])            \
                 : "r"(a0), "r"(a1), "r"(a2), "r"(a3), "r"(b0), "r"(b1))

__device__ __forceinline__ uint32_t packh(__half a, __half b) {
    return (uint32_t)__half_as_ushort(a) | ((uint32_t)__half_as_ushort(b) << 16);
}

// ---------------------------------------------------------------------------
// cp.async one K-chunk (32 fp16) of A and B tiles into a stage (1024 x 16B)
// ---------------------------------------------------------------------------
__device__ __forceinline__ void issue_chunk(
    uint32_t smStage,
    const __half* __restrict__ A, int lda, int rowBase,
    const __half* __restrict__ B, int ldb, int colBase, int k0)
{
    const int tid = threadIdx.x;
#pragma unroll
    for (int i = 0; i < 4; i++) {
        const int id   = tid + 256 * i;    // 0..1023
        const int tile = id >> 9;          // 0: A, 1: B
        const int row  = (id >> 2) & 127;
        const int cc   = id & 3;
        const __half* g = (tile ? B + (size_t)(colBase + row) * ldb
                                : A + (size_t)(rowBase + row) * lda) + k0 + cc * 8;
        cp16(smStage + tile * TILEB + row * ROWB + SWZB(row, cc * 16), g);
    }
    asm volatile("cp.async.commit_group;" ::: "memory");
}

// ---------------------------------------------------------------------------
// compute one stage: 2 k16-steps, warp tile 64x32 (8 warps, 2x4)
// ---------------------------------------------------------------------------
__device__ __forceinline__ void compute_stage(uint32_t sst, int mW, int nW,
                                              int rIn, int cInB,
                                              float acc[4][4][4])
{
#pragma unroll
    for (int ks = 0; ks < 2; ks++) {
        const int cIn = cInB + ks * 32;
        uint32_t bh[2][4];
#pragma unroll
        for (int p = 0; p < 2; p++) {
            const int row = nW + p * 16 + rIn;
            const uint32_t off = (uint32_t)(row * ROWB + SWZB(row, cIn));
            LDSM4(bh[p][0], bh[p][1], bh[p][2], bh[p][3], sst + TILEB + off);
        }
#pragma unroll
        for (int mt = 0; mt < 4; mt++) {
            const int row = mW + mt * 16 + rIn;
            const uint32_t off = (uint32_t)(row * ROWB + SWZB(row, cIn));
            uint32_t ah[4];
            LDSM4(ah[0], ah[1], ah[2], ah[3], sst + off);
#pragma unroll
            for (int nt = 0; nt < 4; nt++) {
                const int p = nt >> 1, s = nt & 1;
                MMA16816(acc[mt][nt], ah[0], ah[1], ah[2], ah[3],
                         bh[p][s], bh[p][s + 2]);
            }
        }
    }
}

// ---------------------------------------------------------------------------
// NT GEMM core: 128x128 tile, 4-stage cp.async ring, one barrier per stage
// ---------------------------------------------------------------------------
__device__ __forceinline__ void gemm_core(
    const __half* __restrict__ A, int lda, int rowBase,
    const __half* __restrict__ B, int ldb, int colBase,
    int Kdim, char* sm, float acc[4][4][4])
{
    const uint32_t smBase = smem_u32(sm);
    const int lane = threadIdx.x & 31;
    const int warp = threadIdx.x >> 5;
    const int mW = (warp >> 2) * 64, nW = (warp & 3) * 32;
    const int grp = lane >> 3;
    const int rIn = (grp & 1) * 8 + (lane & 7);
    const int cInB = (grp >> 1) * 16;

    const int NC = Kdim / BKH;
    issue_chunk(smBase,          A, lda, rowBase, B, ldb, colBase, 0);
    issue_chunk(smBase + STAGEB, A, lda, rowBase, B, ldb, colBase, BKH);

    int stage = 0;
    for (int c = 0; c < NC; c++) {
        if (c + 2 < NC) {
            const int s2 = (stage + 2) & 3;
            issue_chunk(smBase + s2 * STAGEB, A, lda, rowBase,
                        B, ldb, colBase, (c + 2) * BKH);
        } else {
            asm volatile("cp.async.commit_group;" ::: "memory");
        }
        asm volatile("cp.async.wait_group 2;" ::: "memory");
        __syncthreads();
        compute_stage(smBase + stage * STAGEB, mW, nW, rIn, cInB, acc);
        stage = (stage + 1) & 3;
    }
}

// ---------------------------------------------------------------------------
// Kernel 0: fp32 -> fp16 convert for x, Wq, Wk, Wv in ONE launch
// ---------------------------------------------------------------------------
#define NX4 (MTOT * EMBED / 4)        // 2M
#define NW4 (EMBED * EMBED / 4)       // 256K
__global__ __launch_bounds__(256)
void conv_k(const float* __restrict__ x,  const float* __restrict__ Wq,
            const float* __restrict__ Wk, const float* __restrict__ Wv)
{
    const int i = blockIdx.x * 256 + threadIdx.x;
    const float* in; __half* o; int idx;
    if (i < NX4)                { in = x;  o = g_x;           idx = i; }
    else if (i < NX4 + NW4)     { in = Wq; o = g_W;           idx = i - NX4; }
    else if (i < NX4 + 2 * NW4) { in = Wk; o = g_W + 4 * NW4; idx = i - NX4 - NW4; }
    else if (i < NX4 + 3 * NW4) { in = Wv; o = g_W + 8 * NW4; idx = i - NX4 - 2 * NW4; }
    else return;
    float4 v = reinterpret_cast<const float4*>(in)[idx];
    reinterpret_cast<uint2*>(o)[idx] =
        make_uint2(packh(__float2half(v.x), __float2half(v.y)),
                   packh(__float2half(v.z), __float2half(v.w)));
}

// ---------------------------------------------------------------------------
// Kernel 1a: Q/K projection (x @ W^T + b). z: 0=Q, 1=K.
// ---------------------------------------------------------------------------
__global__ __launch_bounds__(NTHREADS, 2)
void qk_k(const float* __restrict__ bq, const float* __restrict__ bk)
{
    extern __shared__ char sm[];
    const int which = blockIdx.z;
    const float* bias = (which == 0) ? bq : bk;
    const __half* W = g_W + (size_t)which * EMBED * EMBED;

    const int rowBase = blockIdx.y * BM;
    const int colBase = blockIdx.x * BN;

    float acc[4][4][4] = {};
    gemm_core(g_x, EMBED, rowBase, W, EMBED, colBase, EMBED, sm, acc);

    const int warp = threadIdx.x >> 5, lane = threadIdx.x & 31;
    const int mW = (warp >> 2) * 64, nW = (warp & 3) * 32;
    __half* o = (which == 0) ? g_Q : g_K;
#pragma unroll
    for (int mt = 0; mt < 4; mt++) {
#pragma unroll
        for (int nt = 0; nt < 4; nt++) {
            const int r0 = rowBase + mW + mt * 16 + (lane >> 2);
            const int c0 = colBase + nW + nt * 8 + 2 * (lane & 3);
            const float b0 = bias[c0], b1 = bias[c0 + 1];
            *reinterpret_cast<uint32_t*>(o + (size_t)r0 * EMBED + c0) =
                packh(__float2half(acc[mt][nt][0] + b0),
                      __float2half(acc[mt][nt][1] + b1));
            *reinterpret_cast<uint32_t*>(o + (size_t)(r0 + 8) * EMBED + c0) =
                packh(__float2half(acc[mt][nt][2] + b0),
                      __float2half(acc[mt][nt][3] + b1));
        }
    }
}

// ---------------------------------------------------------------------------
// Kernel 1b: V projection, written TRANSPOSED into g_Vt (side stream)
// ---------------------------------------------------------------------------
__global__ __launch_bounds__(NTHREADS, 2)
void v_k(const float* __restrict__ bv)
{
    extern __shared__ char sm[];
    const __half* W = g_W + (size_t)2 * EMBED * EMBED;

    const int rowBase = blockIdx.y * BM;
    const int colBase = blockIdx.x * BN;

    float acc[4][4][4] = {};
    gemm_core(g_x, EMBED, rowBase, W, EMBED, colBase, EMBED, sm, acc);

    const int warp = threadIdx.x >> 5, lane = threadIdx.x & 31;
    const int mW = (warp >> 2) * 64, nW = (warp & 3) * 32;

    __syncthreads();
    __half* sh = reinterpret_cast<__half*>(sm);
#pragma unroll
    for (int mt = 0; mt < 4; mt++) {
#pragma unroll
        for (int nt = 0; nt < 4; nt++) {
            const int rr = mW + mt * 16 + (lane >> 2);   // s_rel
            const int cc = nW + nt * 8 + 2 * (lane & 3); // e_rel
            const float b0 = bv[colBase + cc], b1 = bv[colBase + cc + 1];
            sh[cc * 136 + rr]           = __float2half(acc[mt][nt][0] + b0);
            sh[(cc + 1) * 136 + rr]     = __float2half(acc[mt][nt][1] + b1);
            sh[cc * 136 + rr + 8]       = __float2half(acc[mt][nt][2] + b0);
            sh[(cc + 1) * 136 + rr + 8] = __float2half(acc[mt][nt][3] + b1);
        }
    }
    __syncthreads();
    const int b = rowBase >> 11;
    const int sBase = rowBase & (SEQ - 1);
    const int erow = threadIdx.x >> 1, half = threadIdx.x & 1;
    const uint32_t* src = reinterpret_cast<const uint32_t*>(sh + erow * 136 + half * 64);
    const size_t dstE = ((size_t)(b * EMBED + colBase + erow) * SEQ + sBase + half * 64) >> 1;
    uint32_t* d = reinterpret_cast<uint32_t*>(g_Vt) + dstE;
#pragma unroll
    for (int i = 0; i < 32; i++) d[i] = src[i];
}

// ---------------------------------------------------------------------------
// Kernel 2: raw scores, COMPACT triangular grid (136 tiles/batch), heavy-y
// first. u = 135 - bx; y = floor sqrt-ish decode; x = u - y(y+1)/2.
// ---------------------------------------------------------------------------
__global__ __launch_bounds__(NTHREADS, 2)
void scores_k(float* __restrict__ wts)
{
    extern __shared__ char sm[];
    const int b = blockIdx.y;
    const int u = 135 - (int)blockIdx.x;    // heavy rows first
    int y = 0;
    while ((y + 1) * (y + 2) / 2 <= u) y++;
    const int x = u - y * (y + 1) / 2;

    const __half* Q = g_Q + (size_t)b * SEQ * EMBED;
    const __half* K = g_K + (size_t)b * SEQ * EMBED;
    float* S = wts + (size_t)b * SEQ * SEQ;

    const int rowBase = y * BM;
    const int colBase = x * BN;

    float acc[4][4][4] = {};
    gemm_core(Q, EMBED, rowBase, K, EMBED, colBase, EMBED, sm, acc);

    const int warp = threadIdx.x >> 5, lane = threadIdx.x & 31;
    const int mW = (warp >> 2) * 64, nW = (warp & 3) * 32;
    const float scale = 0.03125f;

#pragma unroll
    for (int mt = 0; mt < 4; mt++) {
#pragma unroll
        for (int nt = 0; nt < 4; nt++) {
            const int q0 = rowBase + mW + mt * 16 + (lane >> 2);
            const int c0 = colBase + nW + nt * 8 + 2 * (lane & 3);
            float2 v0, v1;
            v0.x = acc[mt][nt][0] * scale + ((c0 + 0) > q0 ? -999.0f : 0.0f);
            v0.y = acc[mt][nt][1] * scale + ((c0 + 1) > q0 ? -999.0f : 0.0f);
            v1.x = acc[mt][nt][2] * scale + ((c0 + 0) > (q0 + 8) ? -999.0f : 0.0f);
            v1.y = acc[mt][nt][3] * scale + ((c0 + 1) > (q0 + 8) ? -999.0f : 0.0f);
            *(float2*)&S[(size_t)q0 * SEQ + c0]       = v0;
            *(float2*)&S[(size_t)(q0 + 8) * SEQ + c0] = v1;
        }
    }
}

// ---------------------------------------------------------------------------
// Kernel 3: softmax over valid prefix; fp32 wts (+tail zeros) + fp16 prefix
// ---------------------------------------------------------------------------
__global__ __launch_bounds__(256)
void softmax_k(float* __restrict__ wts)
{
    const int row = blockIdx.x;            // b*SEQ + q
    const int q = row & (SEQ - 1);
    const int L = ((q >> 7) + 1) << 7;
    float* p = wts + (size_t)row * SEQ;
    __half* wh = g_w + (size_t)row * SEQ;
    const int t = threadIdx.x;
    __shared__ float red[8];

    float mx = -1e30f;
    for (int k = t; k < L; k += 256) mx = fmaxf(mx, p[k]);
#pragma unroll
    for (int o = 16; o > 0; o >>= 1) mx = fmaxf(mx, __shfl_xor_sync(0xffffffffu, mx, o));
    if ((t & 31) == 0) red[t >> 5] = mx;
    __syncthreads();
    float mxall = red[0];
#pragma unroll
    for (int i = 1; i < 8; i++) mxall = fmaxf(mxall, red[i]);
    __syncthreads();

    float v[8];
    float s = 0.0f;
    {
        int i = 0;
        for (int k = t; k < L; k += 256, i++) { v[i] = __expf(p[k] - mxall); s += v[i]; }
    }
#pragma unroll
    for (int o = 16; o > 0; o >>= 1) s += __shfl_xor_sync(0xffffffffu, s, o);
    if ((t & 31) == 0) red[t >> 5] = s;
    __syncthreads();
    float total = 0.0f;
#pragma unroll
    for (int i = 0; i < 8; i++) total += red[i];
    const float inv = 1.0f / total;

    {
        int i = 0;
        for (int k = t; k < L; k += 256, i++) {
            const float w = v[i] * inv;
            p[k] = w;
            wh[k] = __float2half(w);
        }
    }
    // fp32 tail zeros only (fp16 tail never read: av truncates K at L)
    for (int k = L + t; k < SEQ; k += 256) p[k] = 0.0f;
}

// ---------------------------------------------------------------------------
// Kernel 4: out = w @ V via NT GEMM against Vt; K truncated causally.
// blockIdx.y REVERSED so longest-K CTAs launch first (tail balance).
// ---------------------------------------------------------------------------
__global__ __launch_bounds__(NTHREADS, 2)
void av_k(float* __restrict__ out)
{
    extern __shared__ char sm[];
    const int b = blockIdx.z;
    const __half* A  = g_w  + (size_t)b * SEQ * SEQ;
    const __half* Bv = g_Vt + (size_t)b * EMBED * SEQ;
    float* C = out + (size_t)b * SEQ * EMBED;

    const int by = (SEQ / BM - 1) - blockIdx.y;   // longest K first
    const int rowBase = by * BM;
    const int colBase = blockIdx.x * BN;
    const int Keff = rowBase + BM;                // causal truncation

    float acc[4][4][4] = {};
    gemm_core(A, SEQ, rowBase, Bv, SEQ, colBase, Keff, sm, acc);

    const int warp = threadIdx.x >> 5, lane = threadIdx.x & 31;
    const int mW = (warp >> 2) * 64, nW = (warp & 3) * 32;

#pragma unroll
    for (int mt = 0; mt < 4; mt++) {
#pragma unroll
        for (int nt = 0; nt < 4; nt++) {
            const int r0 = rowBase + mW + mt * 16 + (lane >> 2);
            const int c0 = colBase + nW + nt * 8 + 2 * (lane & 3);
            *(float2*)&C[(size_t)r0 * EMBED + c0] =
                make_float2(acc[mt][nt][0], acc[mt][nt][1]);
            *(float2*)&C[(size_t)(r0 + 8) * EMBED + c0] =
                make_float2(acc[mt][nt][2], acc[mt][nt][3]);
        }
    }
}

// ---------------------------------------------------------------------------
extern "C" void kernel_launch(void* const* d_in, const int* in_sizes, int n_in,
                              void* d_out, int out_size)
{
    const float* x  = (const float*)d_in[0];
    const float* Wq = (const float*)d_in[1];
    const float* bq = (const float*)d_in[2];
    const float* Wk = (const float*)d_in[3];
    const float* bk = (const float*)d_in[4];
    const float* Wv = (const float*)d_in[5];
    const float* bv = (const float*)d_in[6];

    float* out = (float*)d_out;
    float* wts = out + (size_t)MTOT * EMBED;

    // lazily-created host objects (identical launch pattern every call)
    static cudaStream_t s1 = nullptr;
    static cudaEvent_t evFork = nullptr, evJoin = nullptr;
    if (!s1) {
        cudaStreamCreateWithFlags(&s1, cudaStreamNonBlocking);
        cudaEventCreateWithFlags(&evFork, cudaEventDisableTiming);
        cudaEventCreateWithFlags(&evJoin, cudaEventDisableTiming);
        cudaFuncSetAttribute(qk_k,     cudaFuncAttributeMaxDynamicSharedMemorySize, SMEM_DYN);
        cudaFuncSetAttribute(v_k,      cudaFuncAttributeMaxDynamicSharedMemorySize, SMEM_DYN);
        cudaFuncSetAttribute(scores_k, cudaFuncAttributeMaxDynamicSharedMemorySize, SMEM_DYN);
        cudaFuncSetAttribute(av_k,     cudaFuncAttributeMaxDynamicSharedMemorySize, SMEM_DYN);
    }

    const int ntot = NX4 + 3 * NW4;
    conv_k<<<(ntot + 255) / 256, 256>>>(x, Wq, Wk, Wv);

    // fork: V projection on side stream, overlapping QK/scores/softmax
    cudaEventRecord(evFork, 0);
    cudaStreamWaitEvent(s1, evFork, 0);
    v_k<<<dim3(EMBED / BN, MTOT / BM), NTHREADS, SMEM_DYN, s1>>>(bv);
    cudaEventRecord(evJoin, s1);

    qk_k<<<dim3(EMBED / BN, MTOT / BM, 2), NTHREADS, SMEM_DYN>>>(bq, bk);
    scores_k<<<dim3(136, BATCH), NTHREADS, SMEM_DYN>>>(wts);
    softmax_k<<<dim3(MTOT), dim3(256)>>>(wts);

    // join: av needs V and softmax
    cudaStreamWaitEvent(0, evJoin, 0);
    av_k<<<dim3(EMBED / BN, SEQ / BM, BATCH), NTHREADS, SMEM_DYN>>>(out);
}